// round 13
// baseline (speedup 1.0000x reference)
#include <cuda_runtime.h>
#include <cstdint>
#include <float.h>

// Problem shape (fixed by the dataset): P=512, R=256, S=256
#define RR 256
#define SS 256
#define MAXP 512
#define PSTRIDE 260   // K2 panel row stride (floats)

// ---- scratch ----
__device__ float4  g_cpart[MAXP * 4 * SS];   // per-quarter column top-4 partials (8 MB)
__device__ float   g_cthr[MAXP * SS];
__device__ uint8_t g_cflag[MAXP * SS];
__device__ int     g_cidx[MAXP * SS * 3];

// Predicate-free top-4 value tracker: 7 FMNMX.
__device__ __forceinline__ void top4(float v, float& a, float& b, float& c, float& d) {
    float t1 = fminf(a, v);  a = fmaxf(a, v);
    float t2 = fminf(b, t1); b = fmaxf(b, t1);
    float t3 = fminf(c, t2); c = fmaxf(c, t2);
    d = fmaxf(d, t3);
}

// Stable top-3 insert with index (rare tie path): strict '>' + increasing scan
// order reproduces jax.lax.top_k tie-breaking exactly.
__device__ __forceinline__ void ins3i(float v, int i,
                                      float& a, int& ia,
                                      float& b, int& ib,
                                      float& c, int& ic) {
    bool ga = v > a, gb = v > b, gc = v > c;
    c  = gb ? b  : (gc ? v : c);
    ic = gb ? ib : (gc ? i : ic);
    b  = ga ? a  : (gb ? v : b);
    ib = ga ? ia : (gb ? i : ib);
    a  = ga ? v : a;
    ia = ga ? i : ia;
}

// ====== K1: column top-4 partials, 4 blocks per slice (64 rows each) ========
__global__ __launch_bounds__(256)
void k1_colpart(const float* __restrict__ score)
{
    __shared__ float scr[4 * 64 * 16];          // 16 KB merge scratch
    const int p  = blockIdx.x >> 2;
    const int qq = blockIdx.x & 3;              // row quarter [64qq, 64qq+64)
    const int t  = threadIdx.x;
    const int g  = t >> 6;                      // row-phase group 0..3
    const int c4 = (t & 63) * 4;
    const float* base = score + (size_t)p * (RR * SS) + (size_t)qq * 64 * SS;

    float4 A, B, C, D;
    A = B = C = D = make_float4(-FLT_MAX, -FLT_MAX, -FLT_MAX, -FLT_MAX);

    #pragma unroll 8
    for (int k = 0; k < 16; k++) {              // rows g+4k within the quarter
        const int r = g + 4 * k;
        const float4 v = *reinterpret_cast<const float4*>(base + (size_t)r * SS + c4);
        top4(v.x, A.x, B.x, C.x, D.x);
        top4(v.y, A.y, B.y, C.y, D.y);
        top4(v.z, A.z, B.z, C.z, D.z);
        top4(v.w, A.w, B.w, C.w, D.w);
    }

    // publish: [group][colquad][comp*4 + rank]
    {
        const int bi = (g * 64 + (t & 63)) * 16;
        scr[bi+ 0]=A.x; scr[bi+ 1]=B.x; scr[bi+ 2]=C.x; scr[bi+ 3]=D.x;
        scr[bi+ 4]=A.y; scr[bi+ 5]=B.y; scr[bi+ 6]=C.y; scr[bi+ 7]=D.y;
        scr[bi+ 8]=A.z; scr[bi+ 9]=B.z; scr[bi+10]=C.z; scr[bi+11]=D.z;
        scr[bi+12]=A.w; scr[bi+13]=B.w; scr[bi+14]=C.w; scr[bi+15]=D.w;
    }
    __syncthreads();

    // thread t owns column t: merge the 4 group-partials, write quarter partial
    {
        const int cq = t >> 2, comp = t & 3;
        float a = -FLT_MAX, b = -FLT_MAX, c = -FLT_MAX, d = -FLT_MAX;
        #pragma unroll
        for (int gg = 0; gg < 4; gg++) {
            const float* qv = &scr[(gg * 64 + cq) * 16 + comp * 4];
            top4(qv[0], a, b, c, d); top4(qv[1], a, b, c, d);
            top4(qv[2], a, b, c, d); top4(qv[3], a, b, c, d);
        }
        g_cpart[(size_t)(p * 4 + qq) * SS + t] = make_float4(a, b, c, d);
    }
}

// ====== K1b: merge 4 quarter-partials per column -> thresholds ==============
__global__ __launch_bounds__(256)
void k1b_merge(const float* __restrict__ score)
{
    const int p = blockIdx.x;
    const int t = threadIdx.x;                  // column t
    float a = -FLT_MAX, b = -FLT_MAX, c = -FLT_MAX, d = -FLT_MAX;
    #pragma unroll
    for (int qq = 0; qq < 4; qq++) {
        const float4 v = g_cpart[(size_t)(p * 4 + qq) * SS + t];
        top4(v.x, a, b, c, d); top4(v.y, a, b, c, d);
        top4(v.z, a, b, c, d); top4(v.w, a, b, c, d);
    }
    const int gi = p * SS + t;
    g_cthr[gi]  = c;
    const bool f = (c == d);                    // boundary tie
    g_cflag[gi] = f ? 1 : 0;
    if (f) {                                     // rare exact path
        const float* base = score + (size_t)p * (RR * SS);
        float X=-FLT_MAX,Y=-FLT_MAX,Z=-FLT_MAX; int ia=-1,ib=-1,ic=-1;
        for (int r = 0; r < RR; r++)
            ins3i(base[(size_t)r * SS + t], r, X, ia, Y, ib, Z, ic);
        g_cidx[gi*3+0]=ia; g_cidx[gi*3+1]=ib; g_cidx[gi*3+2]=ic;
    }
}

// ====== K2: row top-4 from SMEM panel + emit (single gmem read) =============
// grid = P*8 ; block b -> slice p = P-1-(b>>3) (reverse: L2 reuse of K1 reads),
// panel q = b&7 covering rows [32q, 32q+32).
__global__ __launch_bounds__(256)
void k2_rows_emit(const float* __restrict__ score,
                  const int* __restrict__ refm,
                  const int* __restrict__ srcm,
                  float* __restrict__ out,
                  long long n_total, int P)
{
    __shared__ float   panel[32 * PSTRIDE];
    __shared__ float   rpart[8][32][4];
    __shared__ float   rthr_sh[32];
    __shared__ uint8_t rflag_sh[32];
    __shared__ int     ridx_sh[32][3];
    __shared__ int     rmask_sh[32];

    const int b  = blockIdx.x;
    const int p  = (P - 1) - (b >> 3);
    const int q  = b & 7;
    const int t  = threadIdx.x;
    const int w  = t >> 5;
    const int l  = t & 31;
    const int g  = t >> 6;
    const int c4 = (t & 63) * 4;
    const float* base = score + (size_t)p * (RR * SS) + (size_t)q * 32 * SS;

    #pragma unroll
    for (int k = 0; k < 8; k++) {
        const int r = g + 4 * k;
        uint32_t sa = (uint32_t)__cvta_generic_to_shared(&panel[r * PSTRIDE + c4]);
        const float* ga = base + (size_t)r * SS + c4;
        asm volatile("cp.async.cg.shared.global [%0], [%1], 16;" :: "r"(sa), "l"(ga));
    }
    asm volatile("cp.async.commit_group;");
    if (t < 32) rmask_sh[t] = refm[p * RR + q * 32 + t];
    asm volatile("cp.async.wait_group 0;" ::: "memory");
    __syncthreads();

    // row partials: warp w = cols [32w,32w+32), lane l = panel row l
    {
        float ra = -FLT_MAX, rb = -FLT_MAX, rc = -FLT_MAX, rd = -FLT_MAX;
        #pragma unroll
        for (int j = 0; j < 8; j++) {
            const float4 v = *reinterpret_cast<const float4*>(
                &panel[l * PSTRIDE + 32 * w + 4 * j]);
            top4(v.x, ra, rb, rc, rd);
            top4(v.y, ra, rb, rc, rd);
            top4(v.z, ra, rb, rc, rd);
            top4(v.w, ra, rb, rc, rd);
        }
        rpart[w][l][0] = ra; rpart[w][l][1] = rb;
        rpart[w][l][2] = rc; rpart[w][l][3] = rd;
    }
    __syncthreads();

    if (t < 32) {
        float a = -FLT_MAX, bb = -FLT_MAX, c = -FLT_MAX, d = -FLT_MAX;
        #pragma unroll
        for (int ww = 0; ww < 8; ww++) {
            top4(rpart[ww][t][0], a, bb, c, d);
            top4(rpart[ww][t][1], a, bb, c, d);
            top4(rpart[ww][t][2], a, bb, c, d);
            top4(rpart[ww][t][3], a, bb, c, d);
        }
        rthr_sh[t] = c;
        const bool f = (c == d);
        rflag_sh[t] = f ? 1 : 0;
        if (f) {                                  // rare exact path from SMEM
            float X=-FLT_MAX,Y=-FLT_MAX,Z=-FLT_MAX; int ia=-1,ib=-1,ic=-1;
            for (int s = 0; s < SS; s++)
                ins3i(panel[t * PSTRIDE + s], s, X, ia, Y, ib, Z, ic);
            ridx_sh[t][0]=ia; ridx_sh[t][1]=ib; ridx_sh[t][2]=ic;
        }
    }
    __syncthreads();

    // ---- emit from SMEM ----
    {
        const int s0 = c4;
        const int gi = p * SS + s0;
        const float4 cth4 = *reinterpret_cast<const float4*>(&g_cthr[gi]);
        const uchar4 cf4  = *reinterpret_cast<const uchar4*>(&g_cflag[gi]);
        const uint32_t cflags =
            (uint32_t)(cf4.x != 0) | ((uint32_t)(cf4.y != 0) << 1)
          | ((uint32_t)(cf4.z != 0) << 2) | ((uint32_t)(cf4.w != 0) << 3);
        const int4 sm4 = *reinterpret_cast<const int4*>(&srcm[p * SS + s0]);
        const bool sm0 = sm4.x != 0, sm1 = sm4.y != 0, sm2 = sm4.z != 0, sm3 = sm4.w != 0;

        int ci[4][3];
        if (cflags) {
            #pragma unroll
            for (int k = 0; k < 4; k++) {
                if ((cflags >> k) & 1) {
                    ci[k][0] = g_cidx[(gi+k)*3+0];
                    ci[k][1] = g_cidx[(gi+k)*3+1];
                    ci[k][2] = g_cidx[(gi+k)*3+2];
                } else { ci[k][0] = ci[k][1] = ci[k][2] = -9; }
            }
        }

        float* outs = out + (size_t)p * (RR * SS) + (size_t)q * 32 * SS;
        float* outc = outs + (size_t)n_total;

        #pragma unroll
        for (int k = 0; k < 8; k++) {
            const int rl = g + 4 * k;
            const int rg = q * 32 + rl;
            const float rthr = rthr_sh[rl];
            const bool  rm   = rmask_sh[rl] != 0;
            const float4 v4 = *reinterpret_cast<const float4*>(&panel[rl * PSTRIDE + c4]);

            bool fr0, fr1, fr2, fr3;
            if (!rflag_sh[rl]) {
                fr0 = v4.x >= rthr; fr1 = v4.y >= rthr;
                fr2 = v4.z >= rthr; fr3 = v4.w >= rthr;
            } else {
                const int i0 = ridx_sh[rl][0], i1 = ridx_sh[rl][1], i2 = ridx_sh[rl][2];
                fr0 = (s0+0==i0)|(s0+0==i1)|(s0+0==i2);
                fr1 = (s0+1==i0)|(s0+1==i1)|(s0+1==i2);
                fr2 = (s0+2==i0)|(s0+2==i1)|(s0+2==i2);
                fr3 = (s0+3==i0)|(s0+3==i1)|(s0+3==i2);
            }

            bool fc0 = v4.x >= cth4.x, fc1 = v4.y >= cth4.y,
                 fc2 = v4.z >= cth4.z, fc3 = v4.w >= cth4.w;
            if (cflags) {
                if (cflags & 1) fc0 = (rg==ci[0][0])|(rg==ci[0][1])|(rg==ci[0][2]);
                if (cflags & 2) fc1 = (rg==ci[1][0])|(rg==ci[1][1])|(rg==ci[1][2]);
                if (cflags & 4) fc2 = (rg==ci[2][0])|(rg==ci[2][1])|(rg==ci[2][2]);
                if (cflags & 8) fc3 = (rg==ci[3][0])|(rg==ci[3][1])|(rg==ci[3][2]);
            }

            float4 so, co;
            {
                float e;
                e = __expf(v4.x); so.x = 0.5f*((fr0?e:0.f)+(fc0?e:0.f)); co.x = ((fr0|fc0)&&rm&&sm0)?1.f:0.f;
                e = __expf(v4.y); so.y = 0.5f*((fr1?e:0.f)+(fc1?e:0.f)); co.y = ((fr1|fc1)&&rm&&sm1)?1.f:0.f;
                e = __expf(v4.z); so.z = 0.5f*((fr2?e:0.f)+(fc2?e:0.f)); co.z = ((fr2|fc2)&&rm&&sm2)?1.f:0.f;
                e = __expf(v4.w); so.w = 0.5f*((fr3?e:0.f)+(fc3?e:0.f)); co.w = ((fr3|fc3)&&rm&&sm3)?1.f:0.f;
            }

            const size_t off = (size_t)rl * SS + c4;
            __stcs(reinterpret_cast<float4*>(outs + off), so);
            __stcs(reinterpret_cast<float4*>(outc + off), co);
        }
    }
}

extern "C" void kernel_launch(void* const* d_in, const int* in_sizes, int n_in,
                              void* d_out, int out_size) {
    const float* score = (const float*)d_in[0];
    // d_in[1] = node_corr_scores (unused: conditional=False in reference)
    const int*   refm  = (const int*)d_in[2];   // bool -> int32 in harness
    const int*   srcm  = (const int*)d_in[3];
    float* out = (float*)d_out;

    const long long n_total = (long long)in_sizes[0];   // P*R*S
    const int P = (int)(n_total / (RR * SS));

    k1_colpart<<<P * 4, 256>>>(score);
    k1b_merge<<<P, 256>>>(score);
    k2_rows_emit<<<P * 8, 256>>>(score, refm, srcm, out, n_total, P);
}

// round 14
// speedup vs baseline: 1.1244x; 1.1244x over previous
#include <cuda_runtime.h>
#include <cstdint>
#include <float.h>

// Problem shape (fixed by the dataset): P=512, R=256, S=256
#define RR 256
#define SS 256
#define MAXP 512
#define PSTRIDE 260   // K2 panel row stride (floats)

// ---- scratch: per-quarter column top-4 partials (8 MB) ----
__device__ float4 g_cpart[MAXP * 4 * SS];

// Predicate-free top-4 value tracker: 7 FMNMX.
__device__ __forceinline__ void top4(float v, float& a, float& b, float& c, float& d) {
    float t1 = fminf(a, v);  a = fmaxf(a, v);
    float t2 = fminf(b, t1); b = fmaxf(b, t1);
    float t3 = fminf(c, t2); c = fmaxf(c, t2);
    d = fmaxf(d, t3);
}

// Stable top-3 insert with index (rare tie path): strict '>' + increasing scan
// order reproduces jax.lax.top_k tie-breaking exactly.
__device__ __forceinline__ void ins3i(float v, int i,
                                      float& a, int& ia,
                                      float& b, int& ib,
                                      float& c, int& ic) {
    bool ga = v > a, gb = v > b, gc = v > c;
    c  = gb ? b  : (gc ? v : c);
    ic = gb ? ib : (gc ? i : ic);
    b  = ga ? a  : (gb ? v : b);
    ib = ga ? ia : (gb ? i : ib);
    a  = ga ? v : a;
    ia = ga ? i : ia;
}

// ====== K1: column top-4 partials, 4 blocks per slice (64 rows each) ========
// (identical to the R13 version measured at 28.7us, DRAM 61%)
__global__ __launch_bounds__(256)
void k1_colpart(const float* __restrict__ score)
{
    __shared__ float scr[4 * 64 * 16];          // 16 KB merge scratch
    const int p  = blockIdx.x >> 2;
    const int qq = blockIdx.x & 3;              // row quarter [64qq, 64qq+64)
    const int t  = threadIdx.x;
    const int g  = t >> 6;                      // row-phase group 0..3
    const int c4 = (t & 63) * 4;
    const float* base = score + (size_t)p * (RR * SS) + (size_t)qq * 64 * SS;

    float4 A, B, C, D;
    A = B = C = D = make_float4(-FLT_MAX, -FLT_MAX, -FLT_MAX, -FLT_MAX);

    #pragma unroll 8
    for (int k = 0; k < 16; k++) {              // rows g+4k within the quarter
        const int r = g + 4 * k;
        const float4 v = *reinterpret_cast<const float4*>(base + (size_t)r * SS + c4);
        top4(v.x, A.x, B.x, C.x, D.x);
        top4(v.y, A.y, B.y, C.y, D.y);
        top4(v.z, A.z, B.z, C.z, D.z);
        top4(v.w, A.w, B.w, C.w, D.w);
    }

    // publish: [group][colquad][comp*4 + rank]
    {
        const int bi = (g * 64 + (t & 63)) * 16;
        scr[bi+ 0]=A.x; scr[bi+ 1]=B.x; scr[bi+ 2]=C.x; scr[bi+ 3]=D.x;
        scr[bi+ 4]=A.y; scr[bi+ 5]=B.y; scr[bi+ 6]=C.y; scr[bi+ 7]=D.y;
        scr[bi+ 8]=A.z; scr[bi+ 9]=B.z; scr[bi+10]=C.z; scr[bi+11]=D.z;
        scr[bi+12]=A.w; scr[bi+13]=B.w; scr[bi+14]=C.w; scr[bi+15]=D.w;
    }
    __syncthreads();

    // thread t owns column t: merge the 4 group-partials, write quarter partial
    {
        const int cq = t >> 2, comp = t & 3;
        float a = -FLT_MAX, b = -FLT_MAX, c = -FLT_MAX, d = -FLT_MAX;
        #pragma unroll
        for (int gg = 0; gg < 4; gg++) {
            const float* qv = &scr[(gg * 64 + cq) * 16 + comp * 4];
            top4(qv[0], a, b, c, d); top4(qv[1], a, b, c, d);
            top4(qv[2], a, b, c, d); top4(qv[3], a, b, c, d);
        }
        g_cpart[(size_t)(p * 4 + qq) * SS + t] = make_float4(a, b, c, d);
    }
}

// ====== K2: col merge (in cp.async shadow) + row top-4 + emit ===============
// grid = P*8 ; block b -> slice p = P-1-(b>>3) (reverse: L2 reuse of K1 reads),
// panel q = b&7 covering rows [32q, 32q+32).
__global__ __launch_bounds__(256)
void k2_rows_emit(const float* __restrict__ score,
                  const int* __restrict__ refm,
                  const int* __restrict__ srcm,
                  float* __restrict__ out,
                  long long n_total, int P)
{
    __shared__ float   panel[32 * PSTRIDE];     // 33,280 B
    __shared__ float   rpart[8][32][4];         //  4,096 B
    __shared__ float   rthr_sh[32];
    __shared__ uint8_t rflag_sh[32];
    __shared__ int     ridx_sh[32][3];
    __shared__ int     rmask_sh[32];
    __shared__ float   cthr_sh[SS];             //  1,024 B
    __shared__ uint8_t cflag_sh[SS];            //    256 B
    __shared__ int     cidx_sh[SS][3];          //  3,072 B

    const int b  = blockIdx.x;
    const int p  = (P - 1) - (b >> 3);
    const int q  = b & 7;
    const int t  = threadIdx.x;
    const int w  = t >> 5;
    const int l  = t & 31;
    const int g  = t >> 6;                      // warp-uniform row phase
    const int c4 = (t & 63) * 4;
    const float* slice = score + (size_t)p * (RR * SS);
    const float* base  = slice + (size_t)q * 32 * SS;

    // ---- issue panel load first; merge runs in its shadow ----
    #pragma unroll
    for (int k = 0; k < 8; k++) {
        const int r = g + 4 * k;
        uint32_t sa = (uint32_t)__cvta_generic_to_shared(&panel[r * PSTRIDE + c4]);
        const float* ga = base + (size_t)r * SS + c4;
        asm volatile("cp.async.cg.shared.global [%0], [%1], 16;" :: "r"(sa), "l"(ga));
    }
    asm volatile("cp.async.commit_group;");
    if (t < 32) rmask_sh[t] = refm[p * RR + q * 32 + t];

    // ---- column merge: thread t owns column t (partials are L2-hot) ----
    {
        float a = -FLT_MAX, bb = -FLT_MAX, c = -FLT_MAX, d = -FLT_MAX;
        #pragma unroll
        for (int qq = 0; qq < 4; qq++) {
            const float4 v = g_cpart[(size_t)(p * 4 + qq) * SS + t];
            top4(v.x, a, bb, c, d); top4(v.y, a, bb, c, d);
            top4(v.z, a, bb, c, d); top4(v.w, a, bb, c, d);
        }
        cthr_sh[t] = c;
        const bool f = (c == d);                // boundary tie
        cflag_sh[t] = f ? 1 : 0;
        if (f) {                                 // rare exact path (L2-hot col)
            float X=-FLT_MAX,Y=-FLT_MAX,Z=-FLT_MAX; int ia=-1,ib=-1,ic=-1;
            for (int r = 0; r < RR; r++)
                ins3i(slice[(size_t)r * SS + t], r, X, ia, Y, ib, Z, ic);
            cidx_sh[t][0]=ia; cidx_sh[t][1]=ib; cidx_sh[t][2]=ic;
        }
    }

    asm volatile("cp.async.wait_group 0;" ::: "memory");
    __syncthreads();

    // ---- row partials: warp w = cols [32w,32w+32), lane l = panel row l ----
    {
        float ra = -FLT_MAX, rb = -FLT_MAX, rc = -FLT_MAX, rd = -FLT_MAX;
        #pragma unroll
        for (int j = 0; j < 8; j++) {
            const float4 v = *reinterpret_cast<const float4*>(
                &panel[l * PSTRIDE + 32 * w + 4 * j]);
            top4(v.x, ra, rb, rc, rd);
            top4(v.y, ra, rb, rc, rd);
            top4(v.z, ra, rb, rc, rd);
            top4(v.w, ra, rb, rc, rd);
        }
        rpart[w][l][0] = ra; rpart[w][l][1] = rb;
        rpart[w][l][2] = rc; rpart[w][l][3] = rd;
    }
    __syncthreads();

    // ---- finalize panel row t (threads 0..31) ----
    if (t < 32) {
        float a = -FLT_MAX, bb = -FLT_MAX, c = -FLT_MAX, d = -FLT_MAX;
        #pragma unroll
        for (int ww = 0; ww < 8; ww++) {
            top4(rpart[ww][t][0], a, bb, c, d);
            top4(rpart[ww][t][1], a, bb, c, d);
            top4(rpart[ww][t][2], a, bb, c, d);
            top4(rpart[ww][t][3], a, bb, c, d);
        }
        rthr_sh[t] = c;
        const bool f = (c == d);
        rflag_sh[t] = f ? 1 : 0;
        if (f) {                                  // rare exact path from SMEM
            float X=-FLT_MAX,Y=-FLT_MAX,Z=-FLT_MAX; int ia=-1,ib=-1,ic=-1;
            for (int s = 0; s < SS; s++)
                ins3i(panel[t * PSTRIDE + s], s, X, ia, Y, ib, Z, ic);
            ridx_sh[t][0]=ia; ridx_sh[t][1]=ib; ridx_sh[t][2]=ic;
        }
    }
    __syncthreads();

    // ---- emit from SMEM ----
    {
        const int s0 = c4;
        const float4 cth4 = *reinterpret_cast<const float4*>(&cthr_sh[s0]);
        const uchar4 cf4  = *reinterpret_cast<const uchar4*>(&cflag_sh[s0]);
        const uint32_t cflags =
            (uint32_t)(cf4.x != 0) | ((uint32_t)(cf4.y != 0) << 1)
          | ((uint32_t)(cf4.z != 0) << 2) | ((uint32_t)(cf4.w != 0) << 3);
        const int4 sm4 = *reinterpret_cast<const int4*>(&srcm[p * SS + s0]);
        const bool sm0 = sm4.x != 0, sm1 = sm4.y != 0, sm2 = sm4.z != 0, sm3 = sm4.w != 0;

        int ci[4][3];
        if (cflags) {
            #pragma unroll
            for (int k = 0; k < 4; k++) {
                if ((cflags >> k) & 1) {
                    ci[k][0] = cidx_sh[s0+k][0];
                    ci[k][1] = cidx_sh[s0+k][1];
                    ci[k][2] = cidx_sh[s0+k][2];
                } else { ci[k][0] = ci[k][1] = ci[k][2] = -9; }
            }
        }

        float* outs = out + (size_t)p * (RR * SS) + (size_t)q * 32 * SS;
        float* outc = outs + (size_t)n_total;

        #pragma unroll
        for (int k = 0; k < 8; k++) {
            const int rl = g + 4 * k;             // panel row (warp-uniform)
            const int rg = q * 32 + rl;           // global row in slice
            const float rthr = rthr_sh[rl];
            const bool  rm   = rmask_sh[rl] != 0;
            const float4 v4 = *reinterpret_cast<const float4*>(&panel[rl * PSTRIDE + c4]);

            bool fr0, fr1, fr2, fr3;
            if (!rflag_sh[rl]) {                  // warp-uniform branch
                fr0 = v4.x >= rthr; fr1 = v4.y >= rthr;
                fr2 = v4.z >= rthr; fr3 = v4.w >= rthr;
            } else {
                const int i0 = ridx_sh[rl][0], i1 = ridx_sh[rl][1], i2 = ridx_sh[rl][2];
                fr0 = (s0+0==i0)|(s0+0==i1)|(s0+0==i2);
                fr1 = (s0+1==i0)|(s0+1==i1)|(s0+1==i2);
                fr2 = (s0+2==i0)|(s0+2==i1)|(s0+2==i2);
                fr3 = (s0+3==i0)|(s0+3==i1)|(s0+3==i2);
            }

            bool fc0 = v4.x >= cth4.x, fc1 = v4.y >= cth4.y,
                 fc2 = v4.z >= cth4.z, fc3 = v4.w >= cth4.w;
            if (cflags) {                         // rare
                if (cflags & 1) fc0 = (rg==ci[0][0])|(rg==ci[0][1])|(rg==ci[0][2]);
                if (cflags & 2) fc1 = (rg==ci[1][0])|(rg==ci[1][1])|(rg==ci[1][2]);
                if (cflags & 4) fc2 = (rg==ci[2][0])|(rg==ci[2][1])|(rg==ci[2][2]);
                if (cflags & 8) fc3 = (rg==ci[3][0])|(rg==ci[3][1])|(rg==ci[3][2]);
            }

            float4 so, co;
            {
                float e;
                e = __expf(v4.x); so.x = 0.5f*((fr0?e:0.f)+(fc0?e:0.f)); co.x = ((fr0|fc0)&&rm&&sm0)?1.f:0.f;
                e = __expf(v4.y); so.y = 0.5f*((fr1?e:0.f)+(fc1?e:0.f)); co.y = ((fr1|fc1)&&rm&&sm1)?1.f:0.f;
                e = __expf(v4.z); so.z = 0.5f*((fr2?e:0.f)+(fc2?e:0.f)); co.z = ((fr2|fc2)&&rm&&sm2)?1.f:0.f;
                e = __expf(v4.w); so.w = 0.5f*((fr3?e:0.f)+(fc3?e:0.f)); co.w = ((fr3|fc3)&&rm&&sm3)?1.f:0.f;
            }

            const size_t off = (size_t)rl * SS + c4;
            __stcs(reinterpret_cast<float4*>(outs + off), so);   // evict-first
            __stcs(reinterpret_cast<float4*>(outc + off), co);
        }
    }
}

extern "C" void kernel_launch(void* const* d_in, const int* in_sizes, int n_in,
                              void* d_out, int out_size) {
    const float* score = (const float*)d_in[0];
    // d_in[1] = node_corr_scores (unused: conditional=False in reference)
    const int*   refm  = (const int*)d_in[2];   // bool -> int32 in harness
    const int*   srcm  = (const int*)d_in[3];
    float* out = (float*)d_out;

    const long long n_total = (long long)in_sizes[0];   // P*R*S
    const int P = (int)(n_total / (RR * SS));

    k1_colpart<<<P * 4, 256>>>(score);
    k2_rows_emit<<<P * 8, 256>>>(score, refm, srcm, out, n_total, P);
}